// round 14
// baseline (speedup 1.0000x reference)
#include <cuda_runtime.h>
#include <cstdint>

// MultiStepIFNode: T=16 integrate-and-fire over (16, 32, 128, 32, 32) fp32.
// Per neuron: v += x[t]; spike = (v >= 1); v -= spike.
//
// Converged at the HBM roofline: 512 MiB minimal traffic streams at
// 6.26-6.41 TB/s (~79-80% of spec) across every config tested in R1-R13
// (access width 128/256-bit, occ 21-88%, MLP 2-16, persistent vs waved,
// block 128/256, store default/__stcs/__stwt). Residue = bidirectional
// DRAM bus turnaround/refresh, not SASS-addressable.
//
// R14: final zero-risk granularity point — block 512 (grid 2048), one
// CTA/SM. Completes the block-size axis (128/256/512). All other choices
// = measured best (R5): float4, full-T=16 front-batched loads,
// __ldcs/__stcs streaming.

static constexpr int T_STEPS = 16;

__global__ __launch_bounds__(512, 1) void if_multistep_kernel(
    const float4* __restrict__ x,   // T * n4 float4s
    float4* __restrict__ out,       // T * n4 float4s
    int n4)                         // float4s per timestep (N/4)
{
    const int i = blockIdx.x * blockDim.x + threadIdx.x;

    // Front-batch all 16 loads before any store issues.
    float4 xt[T_STEPS];
    #pragma unroll
    for (int t = 0; t < T_STEPS; t++) {
        xt[t] = __ldcs(&x[(size_t)t * n4 + i]);
    }

    float vx = 0.f, vy = 0.f, vz = 0.f, vw = 0.f;

    #pragma unroll
    for (int t = 0; t < T_STEPS; t++) {
        vx += xt[t].x;
        vy += xt[t].y;
        vz += xt[t].z;
        vw += xt[t].w;

        float4 s;
        s.x = (vx >= 1.0f) ? 1.0f : 0.0f;
        s.y = (vy >= 1.0f) ? 1.0f : 0.0f;
        s.z = (vz >= 1.0f) ? 1.0f : 0.0f;
        s.w = (vw >= 1.0f) ? 1.0f : 0.0f;

        vx -= s.x;
        vy -= s.y;
        vz -= s.z;
        vw -= s.w;

        __stcs(&out[(size_t)t * n4 + i], s);
    }
}

extern "C" void kernel_launch(void* const* d_in, const int* in_sizes, int n_in,
                              void* d_out, int out_size)
{
    const float4* x = (const float4*)d_in[0];
    float4* out = (float4*)d_out;

    int n_per_step = out_size / T_STEPS;   // 4,194,304
    int n4 = n_per_step / 4;               // 1,048,576 (exact multiple of 2048*512)

    const int threads = 512;
    int blocks = n4 / threads;             // 2048, exact
    if_multistep_kernel<<<blocks, threads>>>(x, out, n4);
}

// round 15
// speedup vs baseline: 1.0171x; 1.0171x over previous
#include <cuda_runtime.h>
#include <cstdint>

// MultiStepIFNode: T=16 integrate-and-fire over (16, 32, 128, 32, 32) fp32.
// Per neuron: v += x[t]; spike = (v >= 1); v -= spike.
//
// ===================== CONVERGED FINAL KERNEL =====================
// Pure HBM streaming at the provable traffic minimum: 256 MiB in +
// 256 MiB out. Best measured: 81.98us dur_us (~77us kernel, 6.4 TB/s),
// reproduced 8x in [81.98, 82.69].
//
// Fully closed experiment matrix (R1-R14), every axis measured:
//   block size:    128 ~ 256 (best) > 512 (-2%: lumpy CLC tail)
//   access width:  LDG.128 ~ LDG.256 (neutral; issue traffic halved,
//                  DRAM unchanged -> residue is not request-scheduling)
//   supply:        occ 21-88%, MLP 2-16, persistent vs waved -> <=2%,
//                  persistent -10% (starves chip-level MLP)
//   drain:         __stcs best; __stwt -2.5% (fragments write stream)
// All sane configs: 6.26-6.41 TB/s = ~79-80% of 8 TB/s spec. The ~20%
// DRAM-idle residue is bidirectional-stream bus turnaround/refresh —
// not SASS-addressable. TMA cannot beat this path (LTS/DRAM cap is
// path-independent per B300_MICROARCH).
//
// Structure: one thread owns 4 consecutive neurons (float4). Front-batch
// all 16 timestep loads (contiguous read burst, 16 outstanding LDG.E.128
// evict-first), run the v-recurrence in registers, emit 16 STG.E.128
// evict-first. Fully coalesced; grid exactly covers n4
// (1,048,576 = 4096 x 256) so no bounds guard.

static constexpr int T_STEPS = 16;

__global__ __launch_bounds__(256, 2) void if_multistep_kernel(
    const float4* __restrict__ x,   // T * n4 float4s
    float4* __restrict__ out,       // T * n4 float4s
    int n4)                         // float4s per timestep (N/4)
{
    const int i = blockIdx.x * blockDim.x + threadIdx.x;

    // Front-batch all 16 loads before any store issues.
    float4 xt[T_STEPS];
    #pragma unroll
    for (int t = 0; t < T_STEPS; t++) {
        xt[t] = __ldcs(&x[(size_t)t * n4 + i]);
    }

    float vx = 0.f, vy = 0.f, vz = 0.f, vw = 0.f;

    #pragma unroll
    for (int t = 0; t < T_STEPS; t++) {
        vx += xt[t].x;
        vy += xt[t].y;
        vz += xt[t].z;
        vw += xt[t].w;

        float4 s;
        s.x = (vx >= 1.0f) ? 1.0f : 0.0f;
        s.y = (vy >= 1.0f) ? 1.0f : 0.0f;
        s.z = (vz >= 1.0f) ? 1.0f : 0.0f;
        s.w = (vw >= 1.0f) ? 1.0f : 0.0f;

        vx -= s.x;
        vy -= s.y;
        vz -= s.z;
        vw -= s.w;

        __stcs(&out[(size_t)t * n4 + i], s);
    }
}

extern "C" void kernel_launch(void* const* d_in, const int* in_sizes, int n_in,
                              void* d_out, int out_size)
{
    const float4* x = (const float4*)d_in[0];
    float4* out = (float4*)d_out;

    int n_per_step = out_size / T_STEPS;   // 4,194,304
    int n4 = n_per_step / 4;               // 1,048,576 (exact multiple of 4096*256)

    const int threads = 256;
    int blocks = n4 / threads;             // 4096, exact
    if_multistep_kernel<<<blocks, threads>>>(x, out, n4);
}

// round 16
// speedup vs baseline: 1.0175x; 1.0004x over previous
#include <cuda_runtime.h>
#include <cstdint>

// MultiStepIFNode: T=16 integrate-and-fire over (16, 32, 128, 32, 32) fp32.
// Per neuron: v += x[t]; spike = (v >= 1); v -= spike.
//
// ===================== CONVERGED FINAL KERNEL =====================
// Pure HBM streaming at the provable traffic minimum: 256 MiB in +
// 256 MiB out. Best measured: 81.98us dur_us (~76.5us kernel, 6.4 TB/s),
// reproduced 9x in [81.98, 82.69].
//
// Fully closed experiment matrix (R1-R15), every axis measured:
//   block size:    128 ~ 256 (best) > 512 (-2%: lumpy CLC tail)
//   access width:  LDG.128 ~ LDG.256 (neutral; issue traffic halved,
//                  DRAM unchanged -> residue is not request-scheduling)
//   supply:        occ 21-88%, MLP 2-16, persistent vs waved -> <=2%,
//                  persistent -10% (starves chip-level MLP)
//   drain:         __stcs best; __stwt -2.5% (fragments write stream)
// All sane configs: 6.26-6.41 TB/s = ~79-80% of 8 TB/s spec. The ~20%
// DRAM-idle residue is bidirectional-stream bus turnaround/refresh —
// not SASS-addressable. TMA cannot beat this path (LTS/DRAM cap is
// path-independent per B300_MICROARCH).
//
// Structure: one thread owns 4 consecutive neurons (float4). Front-batch
// all 16 timestep loads (contiguous read burst, 16 outstanding LDG.E.128
// evict-first), run the v-recurrence in registers, emit 16 STG.E.128
// evict-first. Fully coalesced; grid exactly covers n4
// (1,048,576 = 4096 x 256) so no bounds guard.

static constexpr int T_STEPS = 16;

__global__ __launch_bounds__(256, 2) void if_multistep_kernel(
    const float4* __restrict__ x,   // T * n4 float4s
    float4* __restrict__ out,       // T * n4 float4s
    int n4)                         // float4s per timestep (N/4)
{
    const int i = blockIdx.x * blockDim.x + threadIdx.x;

    // Front-batch all 16 loads before any store issues.
    float4 xt[T_STEPS];
    #pragma unroll
    for (int t = 0; t < T_STEPS; t++) {
        xt[t] = __ldcs(&x[(size_t)t * n4 + i]);
    }

    float vx = 0.f, vy = 0.f, vz = 0.f, vw = 0.f;

    #pragma unroll
    for (int t = 0; t < T_STEPS; t++) {
        vx += xt[t].x;
        vy += xt[t].y;
        vz += xt[t].z;
        vw += xt[t].w;

        float4 s;
        s.x = (vx >= 1.0f) ? 1.0f : 0.0f;
        s.y = (vy >= 1.0f) ? 1.0f : 0.0f;
        s.z = (vz >= 1.0f) ? 1.0f : 0.0f;
        s.w = (vw >= 1.0f) ? 1.0f : 0.0f;

        vx -= s.x;
        vy -= s.y;
        vz -= s.z;
        vw -= s.w;

        __stcs(&out[(size_t)t * n4 + i], s);
    }
}

extern "C" void kernel_launch(void* const* d_in, const int* in_sizes, int n_in,
                              void* d_out, int out_size)
{
    const float4* x = (const float4*)d_in[0];
    float4* out = (float4*)d_out;

    int n_per_step = out_size / T_STEPS;   // 4,194,304
    int n4 = n_per_step / 4;               // 1,048,576 (exact multiple of 4096*256)

    const int threads = 256;
    int blocks = n4 / threads;             // 4096, exact
    if_multistep_kernel<<<blocks, threads>>>(x, out, n4);
}

// round 17
// speedup vs baseline: 1.0187x; 1.0012x over previous
#include <cuda_runtime.h>
#include <cstdint>

// MultiStepIFNode: T=16 integrate-and-fire over (16, 32, 128, 32, 32) fp32.
// Per neuron: v += x[t]; spike = (v >= 1); v -= spike.
//
// ===================== CONVERGED FINAL KERNEL =====================
// Pure HBM streaming at the provable traffic minimum: 256 MiB in +
// 256 MiB out. Best measured: 81.98us dur_us (~76.5us kernel, 6.4 TB/s),
// reproduced 10x in [81.98, 82.69].
//
// Fully closed experiment matrix (R1-R16), every axis measured:
//   block size:    128 ~ 256 (best) > 512 (-2%: lumpy CLC tail)
//   access width:  LDG.128 ~ LDG.256 (neutral; issue traffic halved,
//                  DRAM unchanged -> residue is not request-scheduling)
//   supply:        occ 21-88%, MLP 2-16, persistent vs waved -> <=2%,
//                  persistent -10% (starves chip-level MLP)
//   drain:         __stcs best; __stwt -2.5% (fragments write stream)
// All sane configs: 6.23-6.41 TB/s = ~78-80% of 8 TB/s spec. The ~20%
// DRAM-idle residue is bidirectional-stream bus turnaround/refresh —
// not SASS-addressable. TMA cannot beat this path (LTS/DRAM cap is
// path-independent per B300_MICROARCH).
//
// Structure: one thread owns 4 consecutive neurons (float4). Front-batch
// all 16 timestep loads (contiguous read burst, 16 outstanding LDG.E.128
// evict-first), run the v-recurrence in registers, emit 16 STG.E.128
// evict-first. Fully coalesced; grid exactly covers n4
// (1,048,576 = 4096 x 256) so no bounds guard.

static constexpr int T_STEPS = 16;

__global__ __launch_bounds__(256, 2) void if_multistep_kernel(
    const float4* __restrict__ x,   // T * n4 float4s
    float4* __restrict__ out,       // T * n4 float4s
    int n4)                         // float4s per timestep (N/4)
{
    const int i = blockIdx.x * blockDim.x + threadIdx.x;

    // Front-batch all 16 loads before any store issues.
    float4 xt[T_STEPS];
    #pragma unroll
    for (int t = 0; t < T_STEPS; t++) {
        xt[t] = __ldcs(&x[(size_t)t * n4 + i]);
    }

    float vx = 0.f, vy = 0.f, vz = 0.f, vw = 0.f;

    #pragma unroll
    for (int t = 0; t < T_STEPS; t++) {
        vx += xt[t].x;
        vy += xt[t].y;
        vz += xt[t].z;
        vw += xt[t].w;

        float4 s;
        s.x = (vx >= 1.0f) ? 1.0f : 0.0f;
        s.y = (vy >= 1.0f) ? 1.0f : 0.0f;
        s.z = (vz >= 1.0f) ? 1.0f : 0.0f;
        s.w = (vw >= 1.0f) ? 1.0f : 0.0f;

        vx -= s.x;
        vy -= s.y;
        vz -= s.z;
        vw -= s.w;

        __stcs(&out[(size_t)t * n4 + i], s);
    }
}

extern "C" void kernel_launch(void* const* d_in, const int* in_sizes, int n_in,
                              void* d_out, int out_size)
{
    const float4* x = (const float4*)d_in[0];
    float4* out = (float4*)d_out;

    int n_per_step = out_size / T_STEPS;   // 4,194,304
    int n4 = n_per_step / 4;               // 1,048,576 (exact multiple of 4096*256)

    const int threads = 256;
    int blocks = n4 / threads;             // 4096, exact
    if_multistep_kernel<<<blocks, threads>>>(x, out, n4);
}